// round 1
// baseline (speedup 1.0000x reference)
#include <cuda_runtime.h>
#include <cuda_bf16.h>
#include <math_constants.h>

// ===========================================================================
// Chamfer loss between N render points and the FULL 256x256 integer pixel
// grid.
//
// Point-side (min over pixels): closed form — nearest grid coord is the
// rounded+clamped coordinate. O(N).
//
// Pixel-side (min over points): d^2 = |p|^2 + (c_j - 2 p . a_j).
// Per (pixel, point): 2 FFMA + 1 FMNMX, vectorized 2-wide with fma.rn.f32x2
// (FFMA2) over point pairs. |p|^2 added once per pixel, one sqrt per pixel.
// ===========================================================================

#define W_DIM 256
#define H_DIM 256
#define MAXPAIRS 1024          // supports up to 2048 points

__device__ float4 g_A[MAXPAIRS];   // (mx0, mx1, my0, my1) per point pair
__device__ float2 g_C[MAXPAIRS];   // (c0, c1) per point pair
__device__ float  g_sum_points;
__device__ float  g_sum_pixels;

// ---------------- packed f32x2 helpers (FFMA2 via PTX) ---------------------
__device__ __forceinline__ unsigned long long pk2(float a, float b) {
    unsigned long long r;
    asm("mov.b64 %0, {%1, %2};" : "=l"(r) : "f"(a), "f"(b));
    return r;
}
__device__ __forceinline__ void upk2(unsigned long long x, float& a, float& b) {
    asm("mov.b64 {%0, %1}, %2;" : "=f"(a), "=f"(b) : "l"(x));
}
__device__ __forceinline__ unsigned long long fma2(
    unsigned long long a, unsigned long long b, unsigned long long c) {
    unsigned long long d;
    asm("fma.rn.f32x2 %0, %1, %2, %3;" : "=l"(d) : "l"(a), "l"(b), "l"(c));
    return d;
}

// ---------------- kernel 0: zero the accumulators --------------------------
__global__ void init_kernel() {
    g_sum_points = 0.0f;
    g_sum_pixels = 0.0f;
}

// ---------------- kernel 1: transform points + point-side closed form ------
__global__ void prep_kernel(const float* __restrict__ pts, int N, int npairs_pad) {
    int j = blockIdx.x * blockDim.x + threadIdx.x;
    float local = 0.0f;
    if (j < npairs_pad) {
        float mx0 = 0.f, my0 = 0.f, c0 = 1e30f;
        float mx1 = 0.f, my1 = 0.f, c1 = 1e30f;
        int i0 = 2 * j, i1 = 2 * j + 1;
        if (i0 < N) {
            float px = pts[2 * i0], py = pts[2 * i0 + 1];
            mx0 = -2.0f * px; my0 = -2.0f * py; c0 = px * px + py * py;
            float nx = fminf(fmaxf(rintf(px), 0.0f), (float)(W_DIM - 1));
            float ny = fminf(fmaxf(rintf(py), 0.0f), (float)(H_DIM - 1));
            float dx = px - nx, dy = py - ny;
            local += sqrtf(dx * dx + dy * dy);
        }
        if (i1 < N) {
            float px = pts[2 * i1], py = pts[2 * i1 + 1];
            mx1 = -2.0f * px; my1 = -2.0f * py; c1 = px * px + py * py;
            float nx = fminf(fmaxf(rintf(px), 0.0f), (float)(W_DIM - 1));
            float ny = fminf(fmaxf(rintf(py), 0.0f), (float)(H_DIM - 1));
            float dx = px - nx, dy = py - ny;
            local += sqrtf(dx * dx + dy * dy);
        }
        g_A[j] = make_float4(mx0, mx1, my0, my1);
        g_C[j] = make_float2(c0, c1);
    }
    // warp reduce + atomic (few warps total)
    #pragma unroll
    for (int o = 16; o; o >>= 1)
        local += __shfl_down_sync(0xffffffffu, local, o);
    if ((threadIdx.x & 31) == 0 && local != 0.0f)
        atomicAdd(&g_sum_points, local);
}

// ---------------- kernel 2: pixel-side brute force (FFMA2) -----------------
// 128 blocks x 256 threads, 2 pixels per thread (gid and gid + 32768).
__global__ void __launch_bounds__(256) pixel_kernel(int npairs) {
    __shared__ float4 sA[MAXPAIRS];
    __shared__ float2 sC[MAXPAIRS];
    for (int j = threadIdx.x; j < npairs; j += 256) {
        sA[j] = g_A[j];
        sC[j] = g_C[j];
    }
    __syncthreads();

    int gid = blockIdx.x * 256 + threadIdx.x;
    int p0 = gid;
    int p1 = gid + 32768;
    float px0 = (float)(p0 & 255), py0 = (float)(p0 >> 8);
    float px1 = (float)(p1 & 255), py1 = (float)(p1 >> 8);

    const unsigned long long PX0 = pk2(px0, px0);
    const unsigned long long PY0 = pk2(py0, py0);
    const unsigned long long PX1 = pk2(px1, px1);
    const unsigned long long PY1 = pk2(py1, py1);

    float m0a = CUDART_INF_F, m0b = CUDART_INF_F;
    float m1a = CUDART_INF_F, m1b = CUDART_INF_F;

    #pragma unroll 8
    for (int j = 0; j < npairs; ++j) {
        float4 a = sA[j];           // (mx_e, mx_o, my_e, my_o)
        float2 c = sC[j];           // (c_e, c_o)
        unsigned long long AX = pk2(a.x, a.y);
        unsigned long long AY = pk2(a.z, a.w);
        unsigned long long CC = pk2(c.x, c.y);

        unsigned long long t0 = fma2(PX0, AX, fma2(PY0, AY, CC));
        unsigned long long t1 = fma2(PX1, AX, fma2(PY1, AY, CC));

        float u, v;
        upk2(t0, u, v);
        m0a = fminf(m0a, u);
        m0b = fminf(m0b, v);
        upk2(t1, u, v);
        m1a = fminf(m1a, u);
        m1b = fminf(m1b, v);
    }

    float d0 = sqrtf(fmaxf(fminf(m0a, m0b) + px0 * px0 + py0 * py0, 0.0f));
    float d1 = sqrtf(fmaxf(fminf(m1a, m1b) + px1 * px1 + py1 * py1, 0.0f));
    float val = d0 + d1;

    #pragma unroll
    for (int o = 16; o; o >>= 1)
        val += __shfl_down_sync(0xffffffffu, val, o);

    __shared__ float wsum[8];
    if ((threadIdx.x & 31) == 0) wsum[threadIdx.x >> 5] = val;
    __syncthreads();
    if (threadIdx.x < 8) {
        float v = wsum[threadIdx.x];
        #pragma unroll
        for (int o = 4; o; o >>= 1)
            v += __shfl_down_sync(0xffu, v, o);
        if (threadIdx.x == 0) atomicAdd(&g_sum_pixels, v);
    }
}

// ---------------- kernel 3: combine -------------------------------------
__global__ void finish_kernel(float* __restrict__ out) {
    out[0] = g_sum_points + g_sum_pixels;
}

extern "C" void kernel_launch(void* const* d_in, const int* in_sizes, int n_in,
                              void* d_out, int out_size) {
    const float* pts = (const float*)d_in[0];
    int N = in_sizes[0] / 2;                 // number of render points
    if (N > 2 * MAXPAIRS) N = 2 * MAXPAIRS;  // capacity guard (dataset: N=2000)
    int npairs = (N + 1) / 2;
    int npairs_pad = (npairs + 7) & ~7;      // multiple of 8 for clean unroll
    if (npairs_pad > MAXPAIRS) npairs_pad = MAXPAIRS;

    init_kernel<<<1, 1>>>();
    prep_kernel<<<(npairs_pad + 255) / 256, 256>>>(pts, N, npairs_pad);
    pixel_kernel<<<128, 256>>>(npairs_pad);
    finish_kernel<<<1, 1>>>((float*)d_out);
}

// round 2
// speedup vs baseline: 1.5405x; 1.5405x over previous
#include <cuda_runtime.h>
#include <cuda_bf16.h>

// ===========================================================================
// Fused single-kernel Chamfer loss: N points vs full 256x256 pixel grid.
//
//  - Point-side min over pixels: closed form (round+clamp). O(N).
//  - Pixel-side min over points: per-block shared-memory spatial hash
//    (32x32 buckets of 8x8 px) + exact expanding-ring search. After
//    completing ring r, unseen points are >= 8r away => stop when dmin<=8r.
//  - Single launch; last-arriving block combines per-block partials
//    deterministically and resets the arrival counter (graph-replay safe).
// ===========================================================================

#define NB      32          // buckets per axis
#define BSHIFT  3           // 8 px per bucket
#define MAXPTS  2048
#define NBLOCKS 128
#define NTHREADS 256

__device__ float g_partials[NBLOCKS];
__device__ int   g_arrival = 0;

__device__ __forceinline__ float query_min2(float px, float py,
                                            const int* __restrict__ off,
                                            const float2* __restrict__ sp) {
    int bx = ((int)px) >> BSHIFT;
    int by = ((int)py) >> BSHIFT;
    float dmin2 = 3.4e38f;

    auto scan = [&](int b) {
        int i0 = off[b], i1 = off[b + 1];
        for (int i = i0; i < i1; ++i) {
            float2 q = sp[i];
            float dx = px - q.x;
            float dy = py - q.y;
            dmin2 = fminf(dmin2, fmaf(dx, dx, dy * dy));
        }
    };

    for (int r = 0; r < NB; ++r) {
        int xa = bx - r; if (xa < 0) xa = 0;
        int xb = bx + r; if (xb > NB - 1) xb = NB - 1;
        if (r == 0) {
            scan((by << 5) + bx);
        } else {
            int yt = by - r, yb = by + r;
            if (yt >= 0) {
                int rowb = yt << 5;
                for (int x = xa; x <= xb; ++x) scan(rowb + x);
            }
            if (yb <= NB - 1) {
                int rowb = yb << 5;
                for (int x = xa; x <= xb; ++x) scan(rowb + x);
            }
            int ya = by - r + 1; if (ya < 0) ya = 0;
            int yz = by + r - 1; if (yz > NB - 1) yz = NB - 1;
            if (bx - r >= 0) {
                int col = bx - r;
                for (int y = ya; y <= yz; ++y) scan((y << 5) + col);
            }
            if (bx + r <= NB - 1) {
                int col = bx + r;
                for (int y = ya; y <= yz; ++y) scan((y << 5) + col);
            }
        }
        float bd = 8.0f * (float)r;
        if (dmin2 <= bd * bd) break;   // ring-(r+1)+ points are >= 8r away
    }
    return dmin2;
}

__global__ void __launch_bounds__(NTHREADS)
chamfer_fused(const float* __restrict__ pts_raw, int N, float* __restrict__ out) {
    __shared__ int    s_cnt[NB * NB];
    __shared__ int    s_off[NB * NB + 1];
    __shared__ int    s_cur[NB * NB];
    __shared__ float2 s_pts[MAXPTS];
    __shared__ float  s_warp[NTHREADS / 32];
    __shared__ int    s_scan[NTHREADS / 32];
    __shared__ int    s_last;

    const float2* __restrict__ pts = (const float2*)pts_raw;
    int tid  = threadIdx.x;
    int lane = tid & 31;
    int wid  = tid >> 5;

    // ---- phase A: zero bucket counts ----
    #pragma unroll
    for (int k = 0; k < 4; ++k) s_cnt[tid * 4 + k] = 0;
    __syncthreads();

    // ---- phase B: count pass (+ closed-form point-side sum, block 0 only) ----
    float psum = 0.0f;
    for (int i = tid; i < N; i += NTHREADS) {
        float2 p = pts[i];
        int b = ((((int)p.y) >> BSHIFT) << 5) + (((int)p.x) >> BSHIFT);
        atomicAdd(&s_cnt[b], 1);
        if (blockIdx.x == 0) {
            float nx = fminf(fmaxf(rintf(p.x), 0.0f), 255.0f);
            float ny = fminf(fmaxf(rintf(p.y), 0.0f), 255.0f);
            float dx = p.x - nx, dy = p.y - ny;
            psum += sqrtf(fmaf(dx, dx, dy * dy));
        }
    }
    __syncthreads();

    // ---- phase C: exclusive prefix sum over 1024 bucket counts ----
    int c0 = s_cnt[tid * 4], c1 = s_cnt[tid * 4 + 1];
    int c2 = s_cnt[tid * 4 + 2], c3 = s_cnt[tid * 4 + 3];
    int stot = c0 + c1 + c2 + c3;
    int v = stot;
    #pragma unroll
    for (int o = 1; o < 32; o <<= 1) {
        int n = __shfl_up_sync(0xffffffffu, v, o);
        if (lane >= o) v += n;
    }
    if (lane == 31) s_scan[wid] = v;
    __syncthreads();
    if (wid == 0) {
        int w = (lane < NTHREADS / 32) ? s_scan[lane] : 0;
        int vv = w;
        #pragma unroll
        for (int o = 1; o < 8; o <<= 1) {
            int n = __shfl_up_sync(0xffffffffu, vv, o);
            if (lane >= o) vv += n;
        }
        if (lane < NTHREADS / 32) s_scan[lane] = vv - w;   // exclusive
    }
    __syncthreads();
    int base = s_scan[wid] + (v - stot);       // exclusive offset, this thread's 4 bins
    s_off[tid * 4]     = base;
    s_off[tid * 4 + 1] = base + c0;
    s_off[tid * 4 + 2] = base + c0 + c1;
    s_off[tid * 4 + 3] = base + c0 + c1 + c2;
    s_cur[tid * 4]     = base;
    s_cur[tid * 4 + 1] = base + c0;
    s_cur[tid * 4 + 2] = base + c0 + c1;
    s_cur[tid * 4 + 3] = base + c0 + c1 + c2;
    if (tid == NTHREADS - 1) s_off[NB * NB] = base + stot;
    __syncthreads();

    // ---- phase D: scatter points into CSR buckets ----
    for (int i = tid; i < N; i += NTHREADS) {
        float2 p = pts[i];
        int b = ((((int)p.y) >> BSHIFT) << 5) + (((int)p.x) >> BSHIFT);
        int idx = atomicAdd(&s_cur[b], 1);
        s_pts[idx] = p;
    }
    __syncthreads();

    // ---- phase E: pixel-side query (2 pixels per thread) ----
    int p0 = blockIdx.x * NTHREADS + tid;       // 0..32767
    int p1 = p0 + 32768;                        // 32768..65535
    float px0 = (float)(p0 & 255), py0 = (float)(p0 >> 8);
    float px1 = (float)(p1 & 255), py1 = (float)(p1 >> 8);

    float val = sqrtf(query_min2(px0, py0, s_off, s_pts))
              + sqrtf(query_min2(px1, py1, s_off, s_pts))
              + psum;

    // ---- phase F: block reduction ----
    #pragma unroll
    for (int o = 16; o; o >>= 1) val += __shfl_down_sync(0xffffffffu, val, o);
    if (lane == 0) s_warp[wid] = val;
    __syncthreads();
    if (tid == 0) {
        float t = 0.0f;
        #pragma unroll
        for (int w = 0; w < NTHREADS / 32; ++w) t += s_warp[w];
        g_partials[blockIdx.x] = t;
        __threadfence();
        int old = atomicAdd(&g_arrival, 1);
        s_last = (old == NBLOCKS - 1) ? 1 : 0;
    }
    __syncthreads();

    // ---- phase G: last-arriving block combines partials (deterministic) ----
    if (s_last) {
        __threadfence();
        if (wid == 0) {
            float t = 0.0f;
            #pragma unroll
            for (int k = 0; k < NBLOCKS / 32; ++k) t += g_partials[k * 32 + lane];
            #pragma unroll
            for (int o = 16; o; o >>= 1) t += __shfl_down_sync(0xffffffffu, t, o);
            if (lane == 0) {
                out[0] = t;
                g_arrival = 0;     // reset for next graph replay
            }
        }
    }
}

extern "C" void kernel_launch(void* const* d_in, const int* in_sizes, int n_in,
                              void* d_out, int out_size) {
    const float* pts = (const float*)d_in[0];
    int N = in_sizes[0] / 2;
    if (N > MAXPTS) N = MAXPTS;    // capacity guard (dataset: N = 2000)
    chamfer_fused<<<NBLOCKS, NTHREADS>>>(pts, N, (float*)d_out);
}

// round 3
// speedup vs baseline: 1.9363x; 1.2569x over previous
#include <cuda_runtime.h>
#include <cuda_bf16.h>

// ===========================================================================
// Fused single-kernel Chamfer loss: N points vs full 256x256 pixel grid.
//
//  - Point-side min over pixels: closed form (round+clamp). O(N).
//  - Pixel-side min over points: per-block shared-memory spatial hash
//    (32x32 buckets of 8x8 px, CSR) + exact expanding-ring search.
//    WARP-PER-BUCKET: each warp owns one bucket's 64 pixels (2 px/lane),
//    so every lane scans the identical candidate list -> uniform control
//    flow, broadcast LDS, warp-vote ring termination. Exactness: after
//    completing ring r, any unseen point lies outside the pixel rectangle
//    [(bx-r)*8,(bx+r+1)*8) x [(by-r)*8,(by+r+1)*8), so its distance is at
//    least the pixel's margin to that rectangle edge.
//  - Single launch; last-arriving block combines per-block partials
//    deterministically and resets the arrival counter (graph-replay safe).
// ===========================================================================

#define NB      32          // buckets per axis
#define BSHIFT  3           // 8 px per bucket
#define MAXPTS  2048
#define NBLOCKS 128
#define NTHREADS 256

__device__ float g_partials[NBLOCKS];
__device__ int   g_arrival = 0;

__global__ void __launch_bounds__(NTHREADS)
chamfer_fused(const float* __restrict__ pts_raw, int N, float* __restrict__ out) {
    __shared__ int    s_cnt[NB * NB];
    __shared__ int    s_off[NB * NB + 1];
    __shared__ int    s_cur[NB * NB];
    __shared__ float2 s_pts[MAXPTS];
    __shared__ float  s_warp[NTHREADS / 32];
    __shared__ int    s_scan[NTHREADS / 32];
    __shared__ int    s_last;

    const float2* __restrict__ pts = (const float2*)pts_raw;
    int tid  = threadIdx.x;
    int lane = tid & 31;
    int wid  = tid >> 5;

    // ---- phase A: zero bucket counts ----
    #pragma unroll
    for (int k = 0; k < 4; ++k) s_cnt[tid * 4 + k] = 0;
    __syncthreads();

    // ---- phase B: count pass (+ closed-form point-side sum on block 0) ----
    float psum = 0.0f;
    for (int i = tid; i < N; i += NTHREADS) {
        float2 p = pts[i];
        int b = ((((int)p.y) >> BSHIFT) << 5) + (((int)p.x) >> BSHIFT);
        atomicAdd(&s_cnt[b], 1);
        if (blockIdx.x == 0) {
            float nx = fminf(fmaxf(rintf(p.x), 0.0f), 255.0f);
            float ny = fminf(fmaxf(rintf(p.y), 0.0f), 255.0f);
            float dx = p.x - nx, dy = p.y - ny;
            psum += sqrtf(fmaf(dx, dx, dy * dy));
        }
    }
    __syncthreads();

    // ---- phase C: exclusive prefix sum over 1024 bucket counts ----
    int c0 = s_cnt[tid * 4], c1 = s_cnt[tid * 4 + 1];
    int c2 = s_cnt[tid * 4 + 2], c3 = s_cnt[tid * 4 + 3];
    int stot = c0 + c1 + c2 + c3;
    int v = stot;
    #pragma unroll
    for (int o = 1; o < 32; o <<= 1) {
        int n = __shfl_up_sync(0xffffffffu, v, o);
        if (lane >= o) v += n;
    }
    if (lane == 31) s_scan[wid] = v;
    __syncthreads();
    if (wid == 0) {
        int w = (lane < NTHREADS / 32) ? s_scan[lane] : 0;
        int vv = w;
        #pragma unroll
        for (int o = 1; o < 8; o <<= 1) {
            int n = __shfl_up_sync(0xffffffffu, vv, o);
            if (lane >= o) vv += n;
        }
        if (lane < NTHREADS / 32) s_scan[lane] = vv - w;   // exclusive
    }
    __syncthreads();
    int base = s_scan[wid] + (v - stot);
    s_off[tid * 4]     = base;
    s_off[tid * 4 + 1] = base + c0;
    s_off[tid * 4 + 2] = base + c0 + c1;
    s_off[tid * 4 + 3] = base + c0 + c1 + c2;
    s_cur[tid * 4]     = base;
    s_cur[tid * 4 + 1] = base + c0;
    s_cur[tid * 4 + 2] = base + c0 + c1;
    s_cur[tid * 4 + 3] = base + c0 + c1 + c2;
    if (tid == NTHREADS - 1) s_off[NB * NB] = base + stot;
    __syncthreads();

    // ---- phase D: scatter points into CSR buckets (L1-hot reload) ----
    for (int i = tid; i < N; i += NTHREADS) {
        float2 p = pts[i];
        int b = ((((int)p.y) >> BSHIFT) << 5) + (((int)p.x) >> BSHIFT);
        int idx = atomicAdd(&s_cur[b], 1);
        s_pts[idx] = p;
    }
    __syncthreads();

    // ---- phase E: WARP-PER-BUCKET pixel query (uniform, broadcast LDS) ----
    int B  = blockIdx.x * (NTHREADS / 32) + wid;   // bucket id 0..1023
    int bx = B & (NB - 1);
    int by = B >> 5;
    // lane's two pixels within the 8x8 bucket
    float px0 = (float)((bx << BSHIFT) + (lane & 7));
    float py0 = (float)((by << BSHIFT) + (lane >> 3));
    float py1 = py0 + 4.0f;                        // lane+32 -> row +4
    float m0 = 3.4e38f, m1 = 3.4e38f;

    auto scan = [&](int b) {
        int i0 = s_off[b], i1 = s_off[b + 1];      // warp-uniform
        for (int i = i0; i < i1; ++i) {
            float2 q = s_pts[i];                   // broadcast
            float dx = px0 - q.x;
            float dy0 = py0 - q.y;
            float dy1 = py1 - q.y;
            float dxx = dx * dx;
            m0 = fminf(m0, fmaf(dy0, dy0, dxx));
            m1 = fminf(m1, fmaf(dy1, dy1, dxx));
        }
    };

    for (int r = 0; r < NB; ++r) {
        int xa = bx - r; if (xa < 0) xa = 0;
        int xb = bx + r; if (xb > NB - 1) xb = NB - 1;
        if (r == 0) {
            scan((by << 5) + bx);
        } else {
            if (by - r >= 0) {
                int rowb = (by - r) << 5;
                for (int x = xa; x <= xb; ++x) scan(rowb + x);
            }
            if (by + r <= NB - 1) {
                int rowb = (by + r) << 5;
                for (int x = xa; x <= xb; ++x) scan(rowb + x);
            }
            int ya = by - r + 1; if (ya < 0) ya = 0;
            int yz = by + r - 1; if (yz > NB - 1) yz = NB - 1;
            if (bx - r >= 0)
                for (int y = ya; y <= yz; ++y) scan((y << 5) + bx - r);
            if (bx + r <= NB - 1)
                for (int y = ya; y <= yz; ++y) scan((y << 5) + bx + r);
        }
        // exact per-pixel margin to the unscanned region outside the
        // scanned bucket rectangle [(bx-r)*8,(bx+r+1)*8) x [..y..)
        float lx = (float)((bx - r) << BSHIFT);
        float hx = (float)((bx + r + 1) << BSHIFT);
        float ly = (float)((by - r) << BSHIFT);
        float hy = (float)((by + r + 1) << BSHIFT);
        float mgx = fminf(px0 - lx, hx - px0);
        float mg0 = fminf(mgx, fminf(py0 - ly, hy - py0));
        float mg1 = fminf(mgx, fminf(py1 - ly, hy - py1));
        bool done = (m0 <= mg0 * mg0) && (m1 <= mg1 * mg1);
        if (__all_sync(0xffffffffu, done)) break;
    }

    float val = sqrtf(m0) + sqrtf(m1) + psum;

    // ---- phase F: block reduction ----
    #pragma unroll
    for (int o = 16; o; o >>= 1) val += __shfl_down_sync(0xffffffffu, val, o);
    if (lane == 0) s_warp[wid] = val;
    __syncthreads();
    if (tid == 0) {
        float t = 0.0f;
        #pragma unroll
        for (int w = 0; w < NTHREADS / 32; ++w) t += s_warp[w];
        g_partials[blockIdx.x] = t;
        __threadfence();
        int old = atomicAdd(&g_arrival, 1);
        s_last = (old == NBLOCKS - 1) ? 1 : 0;
    }
    __syncthreads();

    // ---- phase G: last-arriving block combines partials (deterministic) ----
    if (s_last) {
        __threadfence();
        if (wid == 0) {
            float t = 0.0f;
            #pragma unroll
            for (int k = 0; k < NBLOCKS / 32; ++k) t += g_partials[k * 32 + lane];
            #pragma unroll
            for (int o = 16; o; o >>= 1) t += __shfl_down_sync(0xffffffffu, t, o);
            if (lane == 0) {
                out[0] = t;
                g_arrival = 0;     // reset for next graph replay
            }
        }
    }
}

extern "C" void kernel_launch(void* const* d_in, const int* in_sizes, int n_in,
                              void* d_out, int out_size) {
    const float* pts = (const float*)d_in[0];
    int N = in_sizes[0] / 2;
    if (N > MAXPTS) N = MAXPTS;    // capacity guard (dataset: N = 2000)
    chamfer_fused<<<NBLOCKS, NTHREADS>>>(pts, N, (float*)d_out);
}

// round 7
// speedup vs baseline: 2.7143x; 1.4018x over previous
#include <cuda_runtime.h>
#include <cuda_bf16.h>

// ===========================================================================
// Fused single-kernel Chamfer loss: N points vs full 256x256 pixel grid.
//
//  - Point-side: closed form (round+clamp nearest grid coord). O(N).
//  - Pixel-side: per-block smem spatial hash (32x32 buckets of 8x8 px, CSR,
//    built from ONE vectorized global read; scatter from registers) + exact
//    expanding-rectangle search, warp-per-bucket (64 px / warp, 2 px/lane).
//    CSR is row-major so each ring row is ONE contiguous candidate range.
//    Exact stop: after scanning bucket rect radius r, any unseen point is
//    outside the pixel rect [(bx-r)*8,(bx+r+1)*8) x [(by-r)*8,(by+r+1)*8);
//    stop when dmin^2 <= margin^2 for all lanes (warp vote).
//  - Single launch; last-arriving block combines per-block partials
//    deterministically and resets the arrival counter (graph-replay safe).
// ===========================================================================

#define NB       32
#define BSHIFT   3
#define MAXPTS   2048
#define NBLOCKS  64
#define NTHREADS 512
#define NWARPS   (NTHREADS / 32)    // 16

__device__ float g_partials[NBLOCKS];
__device__ int   g_arrival = 0;

__global__ void __launch_bounds__(NTHREADS)
chamfer_fused(const float* __restrict__ pts_raw, int N, float* __restrict__ out) {
    __shared__ int    s_cnt[NB * NB];
    __shared__ int    s_off[NB * NB + 1];
    __shared__ int    s_cur[NB * NB];
    __shared__ float2 s_pts[MAXPTS];
    __shared__ float  s_warp[NWARPS];
    __shared__ int    s_scan[NWARPS];
    __shared__ int    s_last;

    int tid  = threadIdx.x;
    int lane = tid & 31;
    int wid  = tid >> 5;

    // ---- A: zero bucket counts ----
    s_cnt[tid]            = 0;
    s_cnt[tid + NTHREADS] = 0;
    __syncthreads();

    // ---- B: ONE vectorized load pass; points stay in registers ----
    const float4* __restrict__ pts4 = (const float4*)pts_raw;
    int nf4 = N >> 1;                       // float4 = 2 points
    float2 P[4];
    int    Pb[4] = {-1, -1, -1, -1};
    float2 Pex;  int Pbex = -1;             // odd-N tail (thread 0)

    #pragma unroll
    for (int k = 0; k < 2; ++k) {
        int idx = tid + k * NTHREADS;
        if (idx < nf4) {
            float4 f = pts4[idx];
            P[2 * k]     = make_float2(f.x, f.y);
            P[2 * k + 1] = make_float2(f.z, f.w);
            Pb[2 * k]     = ((((int)f.y) >> BSHIFT) << 5) + (((int)f.x) >> BSHIFT);
            Pb[2 * k + 1] = ((((int)f.w) >> BSHIFT) << 5) + (((int)f.z) >> BSHIFT);
        }
    }
    if ((N & 1) && tid == 0) {
        Pex = ((const float2*)pts_raw)[N - 1];
        Pbex = ((((int)Pex.y) >> BSHIFT) << 5) + (((int)Pex.x) >> BSHIFT);
    }

    float psum = 0.0f;
    #pragma unroll
    for (int k = 0; k < 4; ++k)
        if (Pb[k] >= 0) {
            atomicAdd(&s_cnt[Pb[k]], 1);
            if (blockIdx.x == 0) {
                float nx = fminf(fmaxf(rintf(P[k].x), 0.0f), 255.0f);
                float ny = fminf(fmaxf(rintf(P[k].y), 0.0f), 255.0f);
                float dx = P[k].x - nx, dy = P[k].y - ny;
                psum += sqrtf(fmaf(dx, dx, dy * dy));
            }
        }
    if (Pbex >= 0) {
        atomicAdd(&s_cnt[Pbex], 1);
        if (blockIdx.x == 0) {
            float nx = fminf(fmaxf(rintf(Pex.x), 0.0f), 255.0f);
            float ny = fminf(fmaxf(rintf(Pex.y), 0.0f), 255.0f);
            float dx = Pex.x - nx, dy = Pex.y - ny;
            psum += sqrtf(fmaf(dx, dx, dy * dy));
        }
    }
    __syncthreads();

    // ---- C: exclusive prefix sum over 1024 counts (2 per thread) ----
    int c0 = s_cnt[2 * tid], c1 = s_cnt[2 * tid + 1];
    int tsum = c0 + c1;
    int v = tsum;
    #pragma unroll
    for (int o = 1; o < 32; o <<= 1) {
        int n = __shfl_up_sync(0xffffffffu, v, o);
        if (lane >= o) v += n;
    }
    if (lane == 31) s_scan[wid] = v;
    __syncthreads();
    if (wid == 0) {
        int w = (lane < NWARPS) ? s_scan[lane] : 0;
        int vv = w;
        #pragma unroll
        for (int o = 1; o < NWARPS; o <<= 1) {
            int n = __shfl_up_sync(0xffffffffu, vv, o);
            if (lane >= o) vv += n;
        }
        if (lane < NWARPS) s_scan[lane] = vv - w;
    }
    __syncthreads();
    int base = s_scan[wid] + (v - tsum);
    s_off[2 * tid]     = base;
    s_off[2 * tid + 1] = base + c0;
    s_cur[2 * tid]     = base;
    s_cur[2 * tid + 1] = base + c0;
    if (tid == NTHREADS - 1) s_off[NB * NB] = base + tsum;
    __syncthreads();

    // ---- D: scatter from registers ----
    #pragma unroll
    for (int k = 0; k < 4; ++k)
        if (Pb[k] >= 0) s_pts[atomicAdd(&s_cur[Pb[k]], 1)] = P[k];
    if (Pbex >= 0) s_pts[atomicAdd(&s_cur[Pbex], 1)] = Pex;
    __syncthreads();

    // ---- E: warp-per-bucket query, row-contiguous ranges ----
    int B  = blockIdx.x * NWARPS + wid;        // bucket 0..1023
    int bx = B & (NB - 1);
    int by = B >> 5;
    float px  = (float)((bx << BSHIFT) + (lane & 7));
    float py0 = (float)((by << BSHIFT) + (lane >> 3));
    float py1 = py0 + 4.0f;
    float m0 = 3.4e38f, m1 = 3.4e38f;

    auto scan_range = [&](int i0, int i1) {
        for (int i = i0; i < i1; ++i) {
            float2 q = s_pts[i];               // broadcast LDS
            float dx  = px - q.x;
            float dy0 = py0 - q.y;
            float dy1 = py1 - q.y;
            float dxx = dx * dx;
            m0 = fminf(m0, fmaf(dy0, dy0, dxx));
            m1 = fminf(m1, fmaf(dy1, dy1, dxx));
        }
    };
    auto scan_row = [&](int y, int xa, int xb) {   // y valid, xa<=xb clamped
        int rb = y << 5;
        scan_range(s_off[rb + xa], s_off[rb + xb + 1]);
    };

    {   // merged rect r=1 (3x3): prefetch all 3 row ranges, then scan
        int xa = bx > 0 ? bx - 1 : 0;
        int xb = bx < NB - 1 ? bx + 1 : NB - 1;
        int ya = by > 0 ? by - 1 : 0;
        int yb = by < NB - 1 ? by + 1 : NB - 1;
        int r0a = 0, r0b = 0, r1a = 0, r1b = 0, r2a = 0, r2b = 0;
        int rb0 = ya << 5;
        r0a = s_off[rb0 + xa]; r0b = s_off[rb0 + xb + 1];
        if (ya + 1 <= yb) {
            int rb1 = (ya + 1) << 5;
            r1a = s_off[rb1 + xa]; r1b = s_off[rb1 + xb + 1];
        }
        if (ya + 2 <= yb) {
            int rb2 = (ya + 2) << 5;
            r2a = s_off[rb2 + xa]; r2b = s_off[rb2 + xb + 1];
        }
        scan_range(r0a, r0b);
        scan_range(r1a, r1b);
        scan_range(r2a, r2b);
    }

    // fast-path vote for the common "done after 3x3" case
    {
        float lx = (float)((bx - 1) << BSHIFT);
        float hx = (float)((bx + 2) << BSHIFT);
        float ly = (float)((by - 1) << BSHIFT);
        float hy = (float)((by + 2) << BSHIFT);
        float mgx = fminf(px - lx, hx - px);
        float mg0 = fminf(mgx, fminf(py0 - ly, hy - py0));
        float mg1 = fminf(mgx, fminf(py1 - ly, hy - py1));
        bool done = (m0 <= mg0 * mg0) && (m1 <= mg1 * mg1);
        if (!__all_sync(0xffffffffu, done)) {
            for (int r = 2; r <= NB; ++r) {
                int xa = bx - r > 0 ? bx - r : 0;
                int xb = bx + r < NB - 1 ? bx + r : NB - 1;
                if (by - r >= 0)      scan_row(by - r, xa, xb);
                if (by + r <= NB - 1) scan_row(by + r, xa, xb);
                int ya = by - r + 1 > 0 ? by - r + 1 : 0;
                int yz = by + r - 1 < NB - 1 ? by + r - 1 : NB - 1;
                if (bx - r >= 0)
                    for (int y = ya; y <= yz; ++y) scan_row(y, bx - r, bx - r);
                if (bx + r <= NB - 1)
                    for (int y = ya; y <= yz; ++y) scan_row(y, bx + r, bx + r);
                float lx2 = (float)((bx - r) << BSHIFT);
                float hx2 = (float)((bx + r + 1) << BSHIFT);
                float ly2 = (float)((by - r) << BSHIFT);
                float hy2 = (float)((by + r + 1) << BSHIFT);
                float mgx2 = fminf(px - lx2, hx2 - px);
                float g0 = fminf(mgx2, fminf(py0 - ly2, hy2 - py0));
                float g1 = fminf(mgx2, fminf(py1 - ly2, hy2 - py1));
                bool d2 = (m0 <= g0 * g0) && (m1 <= g1 * g1);
                if (__all_sync(0xffffffffu, d2)) break;
            }
        }
    }

    float val = sqrtf(m0) + sqrtf(m1) + psum;

    // ---- F: block reduction ----
    #pragma unroll
    for (int o = 16; o; o >>= 1) val += __shfl_down_sync(0xffffffffu, val, o);
    if (lane == 0) s_warp[wid] = val;
    __syncthreads();
    if (tid == 0) {
        float t = 0.0f;
        #pragma unroll
        for (int w = 0; w < NWARPS; ++w) t += s_warp[w];
        g_partials[blockIdx.x] = t;
        __threadfence();
        int old = atomicAdd(&g_arrival, 1);
        s_last = (old == NBLOCKS - 1) ? 1 : 0;
    }
    __syncthreads();

    // ---- G: last-arriving block combines partials (deterministic) ----
    if (s_last && wid == 0) {
        __threadfence();
        float t = g_partials[lane] + g_partials[lane + 32];
        #pragma unroll
        for (int o = 16; o; o >>= 1) t += __shfl_down_sync(0xffffffffu, t, o);
        if (lane == 0) {
            out[0] = t;
            g_arrival = 0;       // reset for next graph replay
        }
    }
}

extern "C" void kernel_launch(void* const* d_in, const int* in_sizes, int n_in,
                              void* d_out, int out_size) {
    const float* pts = (const float*)d_in[0];
    int N = in_sizes[0] / 2;
    if (N > MAXPTS) N = MAXPTS;    // capacity guard (dataset: N = 2000)
    chamfer_fused<<<NBLOCKS, NTHREADS>>>(pts, N, (float*)d_out);
}